// round 16
// baseline (speedup 1.0000x reference)
#include <cuda_runtime.h>
#include <cuda_bf16.h>
#include <cstdint>

// Problem constants
#define BB 2
#define SS 2048
#define DD 1024
#define HH 16
#define HD 64
#define NEG (-1.0e9f)

// Scratch (device globals)
__device__ float g_q[BB * HH * SS * HD];     // [B,H,S,HD]  (tf32-rounded)
__device__ float g_k[BB * HH * SS * HD];
__device__ float g_v[BB * HH * SS * HD];
__device__ float g_att[BB * SS * DD];        // [B,S,D]     (tf32-rounded)
__device__ float g_xc[BB * SS * DD];         // tf32-rounded x
__device__ float g_wq[DD * DD];              // tf32-rounded weights
__device__ float g_wk[DD * DD];
__device__ float g_wv[DD * DD];
__device__ float g_wo[DD * DD];

// ===========================================================================
// helpers
// ===========================================================================
__device__ __forceinline__ uint32_t f2tf32(float f) {
    uint32_t u;
    asm("cvt.rna.tf32.f32 %0, %1;" : "=r"(u) : "f"(f));
    return u;
}
__device__ __forceinline__ float f2tf32f(float f) {
    return __uint_as_float(f2tf32(f));
}

__device__ __forceinline__ uint32_t smem_u32(const void* p) {
    uint32_t a;
    asm("{ .reg .u64 t; cvta.to.shared.u64 t, %1; cvt.u32.u64 %0, t; }"
        : "=r"(a) : "l"(p));
    return a;
}

__device__ __forceinline__ void cp16(uint32_t dst, const void* src) {
    asm volatile("cp.async.ca.shared.global [%0], [%1], 16;"
                 :: "r"(dst), "l"(src));
}
#define CP_COMMIT() asm volatile("cp.async.commit_group;" ::: "memory")
#define CP_WAIT(N)  asm volatile("cp.async.wait_group %0;" :: "n"(N) : "memory")

__device__ __forceinline__ void mma_tf32(
    float* c, uint32_t a0, uint32_t a1, uint32_t a2, uint32_t a3,
    uint32_t b0, uint32_t b1)
{
    asm volatile(
        "mma.sync.aligned.m16n8k8.row.col.f32.tf32.tf32.f32 "
        "{%0,%1,%2,%3}, {%4,%5,%6,%7}, {%8,%9}, {%0,%1,%2,%3};"
        : "+f"(c[0]), "+f"(c[1]), "+f"(c[2]), "+f"(c[3])
        : "r"(a0), "r"(a1), "r"(a2), "r"(a3), "r"(b0), "r"(b1));
}

// ===========================================================================
// merged tf32 pre-round pass (x + 4 weight matrices, one launch)
// ===========================================================================
#define X4 (BB * SS * DD / 4)
#define W4 (DD * DD / 4)

__global__ __launch_bounds__(256) void cvt_all(
    const float* __restrict__ x,
    const float* __restrict__ Wq, const float* __restrict__ Wk,
    const float* __restrict__ Wv, const float* __restrict__ Wo)
{
    int i = blockIdx.x * blockDim.x + threadIdx.x;
    const float4* src;
    float4* dst;
    int off;
    if (i < X4) {
        src = (const float4*)x; dst = (float4*)g_xc; off = i;
    } else {
        int j = i - X4;
        int seg = j / W4;
        off = j - seg * W4;
        src = (seg == 0) ? (const float4*)Wq : (seg == 1) ? (const float4*)Wk
            : (seg == 2) ? (const float4*)Wv : (const float4*)Wo;
        dst = (seg == 0) ? (float4*)g_wq : (seg == 1) ? (float4*)g_wk
            : (seg == 2) ? (float4*)g_wv : (float4*)g_wo;
        if (seg > 3) return;
    }
    float4 v = src[off];
    float4 q;
    q.x = f2tf32f(v.x); q.y = f2tf32f(v.y);
    q.z = f2tf32f(v.z); q.w = f2tf32f(v.w);
    dst[off] = q;
}

// ===========================================================================
// tf32 mma.sync GEMM — R14 exact: 128 threads, warp tile 64x64, BK=32,
// 3-stage cp.async ring, 2 CTAs/SM.
// ===========================================================================
#define STRA 36
#define STRB 136
#define ASZ (128 * STRA)
#define BSZ (32 * STRB)

__device__ __forceinline__ void gemm_issue(
    const float* __restrict__ A, const float* __restrict__ W,
    int m0, int n0, int c, uint32_t as_u, uint32_t bs_u, int tid)
{
#pragma unroll
    for (int i = 0; i < 8; i++) {
        int lin = i * 512 + tid * 4;
        int row = lin >> 5, col = lin & 31;
        cp16(as_u + (uint32_t)(row * STRA + col) * 4,
             A + (size_t)(m0 + row) * DD + c * 32 + col);
        int kr = lin >> 7, nc = lin & 127;
        cp16(bs_u + (uint32_t)(kr * STRB + nc) * 4,
             W + (size_t)(c * 32 + kr) * DD + n0 + nc);
    }
}

__device__ __forceinline__ void tc_mainloop(
    const float* __restrict__ A, const float* __restrict__ W,
    int m0, int n0, float acc[4][8][4], float* AsG, float* BsG)
{
    const int tid = threadIdx.x;
    const int warp = tid >> 5, lane = tid & 31;
    const int wm0 = (warp & 1) * 64;
    const int wn0 = (warp >> 1) * 64;
    const int r = lane >> 2, cq = lane & 3;

    const uint32_t as_u = smem_u32(AsG);
    const uint32_t bs_u = smem_u32(BsG);

#pragma unroll
    for (int mi = 0; mi < 4; mi++)
#pragma unroll
        for (int ni = 0; ni < 8; ni++)
#pragma unroll
            for (int t = 0; t < 4; t++) acc[mi][ni][t] = 0.f;

    gemm_issue(A, W, m0, n0, 0, as_u, bs_u, tid); CP_COMMIT();
    gemm_issue(A, W, m0, n0, 1, as_u + ASZ * 4, bs_u + BSZ * 4, tid); CP_COMMIT();

    for (int c = 0; c < 32; c++) {
        CP_WAIT(1);
        __syncthreads();

        if (c < 30) {
            int s = (c + 2) % 3;
            gemm_issue(A, W, m0, n0, c + 2,
                       as_u + (uint32_t)(s * ASZ) * 4,
                       bs_u + (uint32_t)(s * BSZ) * 4, tid);
        }
        CP_COMMIT();

        const uint32_t* Asu = (const uint32_t*)(AsG + (c % 3) * ASZ);
        const uint32_t* Bsu = (const uint32_t*)(BsG + (c % 3) * BSZ);
#pragma unroll
        for (int ks = 0; ks < 4; ks++) {
            const int k = ks * 8;
            uint32_t af[4][4], bf[8][2];
#pragma unroll
            for (int mi = 0; mi < 4; mi++) {
                int mb = wm0 + mi * 16;
                af[mi][0] = Asu[(mb + r) * STRA + k + cq];
                af[mi][1] = Asu[(mb + r + 8) * STRA + k + cq];
                af[mi][2] = Asu[(mb + r) * STRA + k + cq + 4];
                af[mi][3] = Asu[(mb + r + 8) * STRA + k + cq + 4];
            }
#pragma unroll
            for (int ni = 0; ni < 8; ni++) {
                int nb = wn0 + ni * 8;
                bf[ni][0] = Bsu[(k + cq) * STRB + nb + r];
                bf[ni][1] = Bsu[(k + cq + 4) * STRB + nb + r];
            }
#pragma unroll
            for (int mi = 0; mi < 4; mi++)
#pragma unroll
                for (int ni = 0; ni < 8; ni++)
                    mma_tf32(acc[mi][ni], af[mi][0], af[mi][1], af[mi][2], af[mi][3],
                             bf[ni][0], bf[ni][1]);
        }
    }
}

// ---------------------------------------------------------------------------
__global__ __launch_bounds__(128, 2) void qkv_mma(
    const float* __restrict__ bq, const float* __restrict__ bk,
    const float* __restrict__ bv)
{
    extern __shared__ float dsm[];
    float* AsG = dsm;
    float* BsG = dsm + 3 * ASZ;

    const int z = blockIdx.z;
    const float* __restrict__ W = (z == 0) ? g_wq : (z == 1) ? g_wk : g_wv;
    const float* __restrict__ bias = (z == 0) ? bq : (z == 1) ? bk : bv;
    float* __restrict__ out = (z == 0) ? g_q : (z == 1) ? g_k : g_v;

    const int m0 = blockIdx.y * 128;
    const int n0 = blockIdx.x * 128;

    float acc[4][8][4];
    tc_mainloop(g_xc, W, m0, n0, acc, AsG, BsG);

    const int tid = threadIdx.x;
    const int warp = tid >> 5, lane = tid & 31;
    const int wm0 = (warp & 1) * 64;
    const int wn0 = (warp >> 1) * 64;
    const int r = lane >> 2, cq = lane & 3;

#pragma unroll
    for (int mi = 0; mi < 4; mi++) {
#pragma unroll
        for (int ni = 0; ni < 8; ni++) {
            int ncol = n0 + wn0 + ni * 8 + 2 * cq;
            int h = ncol >> 6, d = ncol & 63;
            float b0v = bias[ncol], b1v = bias[ncol + 1];
#pragma unroll
            for (int half = 0; half < 2; half++) {
                int mrow = m0 + wm0 + mi * 16 + r + half * 8;
                int bidx = mrow >> 11, s = mrow & (SS - 1);
                float2 o;
                o.x = f2tf32f(acc[mi][ni][half * 2 + 0] + b0v);
                o.y = f2tf32f(acc[mi][ni][half * 2 + 1] + b1v);
                *(float2*)(out + (size_t)((bidx * HH + h) * SS + s) * HD + d) = o;
            }
        }
    }
}

// ---------------------------------------------------------------------------
__global__ __launch_bounds__(128, 2) void oproj_mma(
    const float* __restrict__ bo, float* __restrict__ out)
{
    extern __shared__ float dsm[];
    float* AsG = dsm;
    float* BsG = dsm + 3 * ASZ;

    const int m0 = blockIdx.y * 128;
    const int n0 = blockIdx.x * 128;

    float acc[4][8][4];
    tc_mainloop(g_att, g_wo, m0, n0, acc, AsG, BsG);

    const int tid = threadIdx.x;
    const int warp = tid >> 5, lane = tid & 31;
    const int wm0 = (warp & 1) * 64;
    const int wn0 = (warp >> 1) * 64;
    const int r = lane >> 2, cq = lane & 3;

#pragma unroll
    for (int mi = 0; mi < 4; mi++) {
#pragma unroll
        for (int ni = 0; ni < 8; ni++) {
            int ncol = n0 + wn0 + ni * 8 + 2 * cq;
            float b0v = bo[ncol], b1v = bo[ncol + 1];
#pragma unroll
            for (int half = 0; half < 2; half++) {
                int mrow = m0 + wm0 + mi * 16 + r + half * 8;
                float2 o;
                o.x = acc[mi][ni][half * 2 + 0] + b0v;
                o.y = acc[mi][ni][half * 2 + 1] + b1v;
                *(float2*)(out + (size_t)mrow * DD + ncol) = o;
            }
        }
    }
}

// ===========================================================================
// Flash attention, tf32 mma.sync — R14 structure with Q fragments hoisted
// into registers (loaded ONCE; ptxas can't hoist LDS across barriers).
// 128 q-rows, 4 warps, 2-stage KV ring, 1 sync/tile, 2 CTAs/SM.
// ===========================================================================
#define SA 68
#define QR 128
#define KVSTG (2 * 64 * SA)

__global__ __launch_bounds__(128, 2) void attn_mma(const float* __restrict__ mask)
{
    extern __shared__ float smf[];
    float* Qs = smf;                      // [128][SA]
    float* KV = Qs + QR * SA;             // 2 stages x (K[64*SA] + V[64*SA])
    float* Ms = KV + 2 * KVSTG;           // [2048] additive mask row

    const uint32_t* Qu = (const uint32_t*)Qs;
    const uint32_t qs_u = smem_u32(Qs);
    const uint32_t kv_u = smem_u32(KV);

    const int qt = gridDim.x - 1 - blockIdx.x;   // big tiles first
    const int h = blockIdx.y, b = blockIdx.z;
    const int tid = threadIdx.x, warp = tid >> 5, lane = tid & 31;
    const int r = lane >> 2, cq = lane & 3;
    const int wm = warp * 32;                    // 32 rows per warp
    const int q0 = qt * QR;

    const float* kroot = g_k + (size_t)((b * HH + h) * SS) * HD;
    const float* vroot = g_v + (size_t)((b * HH + h) * SS) * HD;

    // Q tile (cp.async): 128 rows x 64, 16 cp16/thread
    const float* qbase = g_q + (size_t)((b * HH + h) * SS + q0) * HD;
#pragma unroll
    for (int p = 0; p < 16; p++) {
        int lin = p * 512 + tid * 4;
        int rr = lin >> 6, dd = lin & 63;
        cp16(qs_u + (uint32_t)(rr * SA + dd) * 4, qbase + rr * 64 + dd);
    }

    auto issue_kv = [&](int jt) {
        int st = jt & 1;
        uint32_t ku = kv_u + (uint32_t)(st * KVSTG) * 4;
        uint32_t vu = ku + (uint32_t)(64 * SA) * 4;
        const float* kb = kroot + (size_t)(jt * 64) * HD;
        const float* vb = vroot + (size_t)(jt * 64) * HD;
#pragma unroll
        for (int p = 0; p < 8; p++) {
            int lin = p * 512 + tid * 4;
            int rr = lin >> 6, dd = lin & 63;
            uint32_t off = (uint32_t)(rr * SA + dd) * 4;
            cp16(ku + off, kb + rr * 64 + dd);
            cp16(vu + off, vb + rr * 64 + dd);
        }
    };

    issue_kv(0);
    CP_COMMIT();     // group: Q + KV0

    // Preload additive mask row (plain stores; visible after prologue sync)
#pragma unroll
    for (int p = 0; p < 16; p++) {
        int idx = p * 128 + tid;
        Ms[idx] = (1.f - mask[b * SS + idx]) * NEG;
    }

    // ---- prologue: wait Q+KV0, hoist Q fragments into registers (once)
    CP_WAIT(0);
    __syncthreads();

    uint32_t qreg[2][8][4];
#pragma unroll
    for (int mi = 0; mi < 2; mi++) {
        int mb = wm + mi * 16;
#pragma unroll
        for (int ks = 0; ks < 8; ks++) {
            const int k = ks * 8;
            qreg[mi][ks][0] = Qu[(mb + r) * SA + k + cq];
            qreg[mi][ks][1] = Qu[(mb + r + 8) * SA + k + cq];
            qreg[mi][ks][2] = Qu[(mb + r) * SA + k + cq + 4];
            qreg[mi][ks][3] = Qu[(mb + r + 8) * SA + k + cq + 4];
        }
    }

    float o[2][8][4];
#pragma unroll
    for (int mi = 0; mi < 2; mi++)
#pragma unroll
        for (int ni = 0; ni < 8; ni++)
#pragma unroll
            for (int t = 0; t < 4; t++) o[mi][ni][t] = 0.f;
    float mst[2][2] = {{-1e30f, -1e30f}, {-1e30f, -1e30f}};
    float lst[2][2] = {{0.f, 0.f}, {0.f, 0.f}};

    const int jt_max = 2 * qt + 1;
    const int rowbase = q0 + wm;
    const int src0 = (lane & ~3) | (cq >> 1);
    const int src1 = src0 + 2;
    const bool oddl = cq & 1;

    for (int jt = 0; jt <= jt_max; jt++) {
        if (jt > 0) {
            CP_WAIT(0);      // KV(jt) resident (issued a full tile ago)
            __syncthreads(); // readers of the other stage (tile jt-1) done
        }
        if (jt < jt_max) { issue_kv(jt + 1); CP_COMMIT(); }

        const uint32_t* Ku = (const uint32_t*)(KV + (jt & 1) * KVSTG);
        const uint32_t* Vu = Ku + 64 * SA;
        const float* madd = Ms + jt * 64;

        float2 m2[8];
#pragma unroll
        for (int ni = 0; ni < 8; ni++)
            m2[ni] = *(const float2*)&madd[8 * ni + 2 * cq];

        // ---- S = Q @ K^T  (Q from registers)
        float s[2][8][4];
#pragma unroll
        for (int mi = 0; mi < 2; mi++)
#pragma unroll
            for (int ni = 0; ni < 8; ni++)
#pragma unroll
                for (int t = 0; t < 4; t++) s[mi][ni][t] = 0.f;
#pragma unroll
        for (int ks = 0; ks < 8; ks++) {
            const int k = ks * 8;
#pragma unroll
            for (int ni = 0; ni < 8; ni++) {
                uint32_t b0 = Ku[(8 * ni + r) * SA + k + cq];
                uint32_t b1 = Ku[(8 * ni + r) * SA + k + cq + 4];
                mma_tf32(s[0][ni], qreg[0][ks][0], qreg[0][ks][1],
                         qreg[0][ks][2], qreg[0][ks][3], b0, b1);
                mma_tf32(s[1][ni], qreg[1][ks][0], qreg[1][ks][1],
                         qreg[1][ks][2], qreg[1][ks][3], b0, b1);
            }
        }

        // ---- scale + causal + padding mask (warp-uniform fast path)
        const bool part = (jt * 64 + 63 > rowbase);
        if (!part) {
#pragma unroll
            for (int mi = 0; mi < 2; mi++)
#pragma unroll
                for (int ni = 0; ni < 8; ni++) {
                    s[mi][ni][0] = s[mi][ni][0] * 0.125f + m2[ni].x;
                    s[mi][ni][1] = s[mi][ni][1] * 0.125f + m2[ni].y;
                    s[mi][ni][2] = s[mi][ni][2] * 0.125f + m2[ni].x;
                    s[mi][ni][3] = s[mi][ni][3] * 0.125f + m2[ni].y;
                }
        } else {
            const int colb = jt * 64;
#pragma unroll
            for (int mi = 0; mi < 2; mi++) {
#pragma unroll
                for (int ni = 0; ni < 8; ni++) {
#pragma unroll
                    for (int t = 0; t < 4; t++) {
                        int col = 8 * ni + 2 * cq + (t & 1);
                        int rowg = rowbase + mi * 16 + r + ((t < 2) ? 0 : 8);
                        float mv = (t & 1) ? m2[ni].y : m2[ni].x;
                        float v;
                        if (colb + col > rowg) v = NEG + mv;
                        else                   v = s[mi][ni][t] * 0.125f + mv;
                        s[mi][ni][t] = v;
                    }
                }
            }
        }

        // ---- online softmax
#pragma unroll
        for (int mi = 0; mi < 2; mi++) {
            float mx0 = -1e30f, mx1 = -1e30f;
#pragma unroll
            for (int ni = 0; ni < 8; ni++) {
                mx0 = fmaxf(mx0, fmaxf(s[mi][ni][0], s[mi][ni][1]));
                mx1 = fmaxf(mx1, fmaxf(s[mi][ni][2], s[mi][ni][3]));
            }
            mx0 = fmaxf(mx0, __shfl_xor_sync(0xffffffff, mx0, 1));
            mx0 = fmaxf(mx0, __shfl_xor_sync(0xffffffff, mx0, 2));
            mx1 = fmaxf(mx1, __shfl_xor_sync(0xffffffff, mx1, 1));
            mx1 = fmaxf(mx1, __shfl_xor_sync(0xffffffff, mx1, 2));

            float nm0 = fmaxf(mst[mi][0], mx0), nm1 = fmaxf(mst[mi][1], mx1);
            float sc0 = __expf(mst[mi][0] - nm0), sc1 = __expf(mst[mi][1] - nm1);
            float sum0 = 0.f, sum1 = 0.f;
#pragma unroll
            for (int ni = 0; ni < 8; ni++) {
                s[mi][ni][0] = __expf(s[mi][ni][0] - nm0);
                s[mi][ni][1] = __expf(s[mi][ni][1] - nm0);
                s[mi][ni][2] = __expf(s[mi][ni][2] - nm1);
                s[mi][ni][3] = __expf(s[mi][ni][3] - nm1);
                sum0 += s[mi][ni][0] + s[mi][ni][1];
                sum1 += s[mi][ni][2] + s[mi][ni][3];
            }
            sum0 += __shfl_xor_sync(0xffffffff, sum0, 1);
            sum0 += __shfl_xor_sync(0xffffffff, sum0, 2);
            sum1 += __shfl_xor_sync(0xffffffff, sum1, 1);
            sum1 += __shfl_xor_sync(0xffffffff, sum1, 2);

            lst[mi][0] = lst[mi][0] * sc0 + sum0;  mst[mi][0] = nm0;
            lst[mi][1] = lst[mi][1] * sc1 + sum1;  mst[mi][1] = nm1;

#pragma unroll
            for (int ni = 0; ni < 8; ni++) {
                o[mi][ni][0] *= sc0; o[mi][ni][1] *= sc0;
                o[mi][ni][2] *= sc1; o[mi][ni][3] *= sc1;
            }
        }

        // ---- O += P @ V : shuffle C->A fragment conversion; V shared by mi
#pragma unroll
        for (int ks = 0; ks < 8; ks++) {
            uint32_t pa0[2], pa1[2], pa2[2], pa3[2];
#pragma unroll
            for (int mi = 0; mi < 2; mi++) {
                uint32_t q0r = f2tf32(s[mi][ks][0]), q1r = f2tf32(s[mi][ks][1]);
                uint32_t q2r = f2tf32(s[mi][ks][2]), q3r = f2tf32(s[mi][ks][3]);
                uint32_t x00 = __shfl_sync(0xffffffff, q0r, src0);
                uint32_t x01 = __shfl_sync(0xffffffff, q1r, src0);
                uint32_t x10 = __shfl_sync(0xffffffff, q2r, src0);
                uint32_t x11 = __shfl_sync(0xffffffff, q3r, src0);
                uint32_t x20 = __shfl_sync(0xffffffff, q0r, src1);
                uint32_t x21 = __shfl_sync(0xffffffff, q1r, src1);
                uint32_t x30 = __shfl_sync(0xffffffff, q2r, src1);
                uint32_t x31 = __shfl_sync(0xffffffff, q3r, src1);
                pa0[mi] = oddl ? x01 : x00;
                pa1[mi] = oddl ? x11 : x10;
                pa2[mi] = oddl ? x21 : x20;
                pa3[mi] = oddl ? x31 : x30;
            }
            const int k = ks * 8;
#pragma unroll
            for (int ni = 0; ni < 8; ni++) {
                uint32_t b0 = Vu[(k + cq) * SA + 8 * ni + r];
                uint32_t b1 = Vu[(k + cq + 4) * SA + 8 * ni + r];
                mma_tf32(o[0][ni], pa0[0], pa1[0], pa2[0], pa3[0], b0, b1);
                mma_tf32(o[1][ni], pa0[1], pa1[1], pa2[1], pa3[1], b0, b1);
            }
        }
    }

    // ---- epilogue
#pragma unroll
    for (int mi = 0; mi < 2; mi++) {
        float inv0 = 1.f / lst[mi][0], inv1 = 1.f / lst[mi][1];
        int rw0 = rowbase + mi * 16 + r;
        float* ob0 = g_att + (size_t)(b * SS + rw0) * DD + h * HD;
        float* ob1 = g_att + (size_t)(b * SS + rw0 + 8) * DD + h * HD;
#pragma unroll
        for (int ni = 0; ni < 8; ni++) {
            int col = 8 * ni + 2 * cq;
            float2 w0, w1;
            w0.x = f2tf32f(o[mi][ni][0] * inv0); w0.y = f2tf32f(o[mi][ni][1] * inv0);
            w1.x = f2tf32f(o[mi][ni][2] * inv1); w1.y = f2tf32f(o[mi][ni][3] * inv1);
            *(float2*)(ob0 + col) = w0;
            *(float2*)(ob1 + col) = w1;
        }
    }
}

// ---------------------------------------------------------------------------
extern "C" void kernel_launch(void* const* d_in, const int* in_sizes, int n_in,
                              void* d_out, int out_size)
{
    const float* x    = (const float*)d_in[0];
    const float* mask = (const float*)d_in[1];
    const float* Wq   = (const float*)d_in[2];
    const float* bq   = (const float*)d_in[3];
    const float* Wk   = (const float*)d_in[4];
    const float* bk   = (const float*)d_in[5];
    const float* Wv   = (const float*)d_in[6];
    const float* bv   = (const float*)d_in[7];
    const float* Wo   = (const float*)d_in[8];
    const float* bo   = (const float*)d_in[9];
    float* out = (float*)d_out;

    const int cvt_total = X4 + 4 * W4;
    cvt_all<<<(cvt_total + 255) / 256, 256>>>(x, Wq, Wk, Wv, Wo);

    const int gemm_smem = 3 * (ASZ + BSZ) * sizeof(float);                 // ~107.5 KB
    const int attn_smem = (QR * SA + 2 * KVSTG + SS) * sizeof(float);      // ~110 KB
    cudaFuncSetAttribute(qkv_mma,   cudaFuncAttributeMaxDynamicSharedMemorySize, gemm_smem);
    cudaFuncSetAttribute(oproj_mma, cudaFuncAttributeMaxDynamicSharedMemorySize, gemm_smem);
    cudaFuncSetAttribute(attn_mma,  cudaFuncAttributeMaxDynamicSharedMemorySize, attn_smem);

    dim3 gq(DD / 128, (BB * SS) / 128, 3);
    qkv_mma<<<gq, 128, gemm_smem>>>(bq, bk, bv);

    dim3 ga(SS / QR, HH, BB);
    attn_mma<<<ga, 128, attn_smem>>>(mask);

    dim3 go(DD / 128, (BB * SS) / 128);
    oproj_mma<<<go, 128, gemm_smem>>>(bo, out);
}

// round 17
// speedup vs baseline: 1.0384x; 1.0384x over previous
#include <cuda_runtime.h>
#include <cuda_bf16.h>
#include <cstdint>

// Problem constants
#define BB 2
#define SS 2048
#define DD 1024
#define HH 16
#define HD 64
#define NEG (-1.0e9f)

// Scratch (device globals)
__device__ float g_q[BB * HH * SS * HD];     // [B,H,S,HD]  (tf32-rounded)
__device__ float g_k[BB * HH * SS * HD];
__device__ float g_v[BB * HH * SS * HD];
__device__ float g_att[BB * SS * DD];        // [B,S,D]     (tf32-rounded)
__device__ float g_xc[BB * SS * DD];         // tf32-rounded x
__device__ float g_wq[DD * DD];              // tf32-rounded weights
__device__ float g_wk[DD * DD];
__device__ float g_wv[DD * DD];
__device__ float g_wo[DD * DD];

// ===========================================================================
// helpers
// ===========================================================================
__device__ __forceinline__ uint32_t f2tf32(float f) {
    uint32_t u;
    asm("cvt.rna.tf32.f32 %0, %1;" : "=r"(u) : "f"(f));
    return u;
}
__device__ __forceinline__ float f2tf32f(float f) {
    return __uint_as_float(f2tf32(f));
}

__device__ __forceinline__ uint32_t smem_u32(const void* p) {
    uint32_t a;
    asm("{ .reg .u64 t; cvta.to.shared.u64 t, %1; cvt.u32.u64 %0, t; }"
        : "=r"(a) : "l"(p));
    return a;
}

__device__ __forceinline__ void cp16(uint32_t dst, const void* src) {
    asm volatile("cp.async.ca.shared.global [%0], [%1], 16;"
                 :: "r"(dst), "l"(src));
}
#define CP_COMMIT() asm volatile("cp.async.commit_group;" ::: "memory")
#define CP_WAIT(N)  asm volatile("cp.async.wait_group %0;" :: "n"(N) : "memory")

__device__ __forceinline__ void mma_tf32(
    float* c, uint32_t a0, uint32_t a1, uint32_t a2, uint32_t a3,
    uint32_t b0, uint32_t b1)
{
    asm volatile(
        "mma.sync.aligned.m16n8k8.row.col.f32.tf32.tf32.f32 "
        "{%0,%1,%2,%3}, {%4,%5,%6,%7}, {%8,%9}, {%0,%1,%2,%3};"
        : "+f"(c[0]), "+f"(c[1]), "+f"(c[2]), "+f"(c[3])
        : "r"(a0), "r"(a1), "r"(a2), "r"(a3), "r"(b0), "r"(b1));
}

// ===========================================================================
// merged tf32 pre-round pass (x + 4 weight matrices, one launch)
// ===========================================================================
#define X4 (BB * SS * DD / 4)
#define W4 (DD * DD / 4)

__global__ __launch_bounds__(256) void cvt_all(
    const float* __restrict__ x,
    const float* __restrict__ Wq, const float* __restrict__ Wk,
    const float* __restrict__ Wv, const float* __restrict__ Wo)
{
    int i = blockIdx.x * blockDim.x + threadIdx.x;
    const float4* src;
    float4* dst;
    int off;
    if (i < X4) {
        src = (const float4*)x; dst = (float4*)g_xc; off = i;
    } else {
        int j = i - X4;
        int seg = j / W4;
        off = j - seg * W4;
        src = (seg == 0) ? (const float4*)Wq : (seg == 1) ? (const float4*)Wk
            : (seg == 2) ? (const float4*)Wv : (const float4*)Wo;
        dst = (seg == 0) ? (float4*)g_wq : (seg == 1) ? (float4*)g_wk
            : (seg == 2) ? (float4*)g_wv : (float4*)g_wo;
        if (seg > 3) return;
    }
    float4 v = src[off];
    float4 q;
    q.x = f2tf32f(v.x); q.y = f2tf32f(v.y);
    q.z = f2tf32f(v.z); q.w = f2tf32f(v.w);
    dst[off] = q;
}

// ===========================================================================
// tf32 mma.sync GEMM: 128 threads, warp tile 64x64, BK=32,
// 3-stage cp.async ring, 2 CTAs/SM.
// ===========================================================================
#define STRA 36
#define STRB 136
#define ASZ (128 * STRA)
#define BSZ (32 * STRB)

__device__ __forceinline__ void gemm_issue(
    const float* __restrict__ A, const float* __restrict__ W,
    int m0, int n0, int c, uint32_t as_u, uint32_t bs_u, int tid)
{
#pragma unroll
    for (int i = 0; i < 8; i++) {
        int lin = i * 512 + tid * 4;
        int row = lin >> 5, col = lin & 31;
        cp16(as_u + (uint32_t)(row * STRA + col) * 4,
             A + (size_t)(m0 + row) * DD + c * 32 + col);
        int kr = lin >> 7, nc = lin & 127;
        cp16(bs_u + (uint32_t)(kr * STRB + nc) * 4,
             W + (size_t)(c * 32 + kr) * DD + n0 + nc);
    }
}

__device__ __forceinline__ void tc_mainloop(
    const float* __restrict__ A, const float* __restrict__ W,
    int m0, int n0, float acc[4][8][4], float* AsG, float* BsG)
{
    const int tid = threadIdx.x;
    const int warp = tid >> 5, lane = tid & 31;
    const int wm0 = (warp & 1) * 64;
    const int wn0 = (warp >> 1) * 64;
    const int r = lane >> 2, cq = lane & 3;

    const uint32_t as_u = smem_u32(AsG);
    const uint32_t bs_u = smem_u32(BsG);

#pragma unroll
    for (int mi = 0; mi < 4; mi++)
#pragma unroll
        for (int ni = 0; ni < 8; ni++)
#pragma unroll
            for (int t = 0; t < 4; t++) acc[mi][ni][t] = 0.f;

    gemm_issue(A, W, m0, n0, 0, as_u, bs_u, tid); CP_COMMIT();
    gemm_issue(A, W, m0, n0, 1, as_u + ASZ * 4, bs_u + BSZ * 4, tid); CP_COMMIT();

    for (int c = 0; c < 32; c++) {
        CP_WAIT(1);
        __syncthreads();

        if (c < 30) {
            int s = (c + 2) % 3;
            gemm_issue(A, W, m0, n0, c + 2,
                       as_u + (uint32_t)(s * ASZ) * 4,
                       bs_u + (uint32_t)(s * BSZ) * 4, tid);
        }
        CP_COMMIT();

        const uint32_t* Asu = (const uint32_t*)(AsG + (c % 3) * ASZ);
        const uint32_t* Bsu = (const uint32_t*)(BsG + (c % 3) * BSZ);
#pragma unroll
        for (int ks = 0; ks < 4; ks++) {
            const int k = ks * 8;
            uint32_t af[4][4], bf[8][2];
#pragma unroll
            for (int mi = 0; mi < 4; mi++) {
                int mb = wm0 + mi * 16;
                af[mi][0] = Asu[(mb + r) * STRA + k + cq];
                af[mi][1] = Asu[(mb + r + 8) * STRA + k + cq];
                af[mi][2] = Asu[(mb + r) * STRA + k + cq + 4];
                af[mi][3] = Asu[(mb + r + 8) * STRA + k + cq + 4];
            }
#pragma unroll
            for (int ni = 0; ni < 8; ni++) {
                int nb = wn0 + ni * 8;
                bf[ni][0] = Bsu[(k + cq) * STRB + nb + r];
                bf[ni][1] = Bsu[(k + cq + 4) * STRB + nb + r];
            }
#pragma unroll
            for (int mi = 0; mi < 4; mi++)
#pragma unroll
                for (int ni = 0; ni < 8; ni++)
                    mma_tf32(acc[mi][ni], af[mi][0], af[mi][1], af[mi][2], af[mi][3],
                             bf[ni][0], bf[ni][1]);
        }
    }
}

// ---------------------------------------------------------------------------
__global__ __launch_bounds__(128, 2) void qkv_mma(
    const float* __restrict__ bq, const float* __restrict__ bk,
    const float* __restrict__ bv)
{
    extern __shared__ float dsm[];
    float* AsG = dsm;
    float* BsG = dsm + 3 * ASZ;

    const int z = blockIdx.z;
    const float* __restrict__ W = (z == 0) ? g_wq : (z == 1) ? g_wk : g_wv;
    const float* __restrict__ bias = (z == 0) ? bq : (z == 1) ? bk : bv;
    float* __restrict__ out = (z == 0) ? g_q : (z == 1) ? g_k : g_v;

    const int m0 = blockIdx.y * 128;
    const int n0 = blockIdx.x * 128;

    float acc[4][8][4];
    tc_mainloop(g_xc, W, m0, n0, acc, AsG, BsG);

    const int tid = threadIdx.x;
    const int warp = tid >> 5, lane = tid & 31;
    const int wm0 = (warp & 1) * 64;
    const int wn0 = (warp >> 1) * 64;
    const int r = lane >> 2, cq = lane & 3;

#pragma unroll
    for (int mi = 0; mi < 4; mi++) {
#pragma unroll
        for (int ni = 0; ni < 8; ni++) {
            int ncol = n0 + wn0 + ni * 8 + 2 * cq;
            int h = ncol >> 6, d = ncol & 63;
            float b0v = bias[ncol], b1v = bias[ncol + 1];
#pragma unroll
            for (int half = 0; half < 2; half++) {
                int mrow = m0 + wm0 + mi * 16 + r + half * 8;
                int bidx = mrow >> 11, s = mrow & (SS - 1);
                float2 o;
                o.x = f2tf32f(acc[mi][ni][half * 2 + 0] + b0v);
                o.y = f2tf32f(acc[mi][ni][half * 2 + 1] + b1v);
                *(float2*)(out + (size_t)((bidx * HH + h) * SS + s) * HD + d) = o;
            }
        }
    }
}

// ---------------------------------------------------------------------------
__global__ __launch_bounds__(128, 2) void oproj_mma(
    const float* __restrict__ bo, float* __restrict__ out)
{
    extern __shared__ float dsm[];
    float* AsG = dsm;
    float* BsG = dsm + 3 * ASZ;

    const int m0 = blockIdx.y * 128;
    const int n0 = blockIdx.x * 128;

    float acc[4][8][4];
    tc_mainloop(g_att, g_wo, m0, n0, acc, AsG, BsG);

    const int tid = threadIdx.x;
    const int warp = tid >> 5, lane = tid & 31;
    const int wm0 = (warp & 1) * 64;
    const int wn0 = (warp >> 1) * 64;
    const int r = lane >> 2, cq = lane & 3;

#pragma unroll
    for (int mi = 0; mi < 4; mi++) {
#pragma unroll
        for (int ni = 0; ni < 8; ni++) {
            int ncol = n0 + wn0 + ni * 8 + 2 * cq;
            float b0v = bo[ncol], b1v = bo[ncol + 1];
#pragma unroll
            for (int half = 0; half < 2; half++) {
                int mrow = m0 + wm0 + mi * 16 + r + half * 8;
                float2 o;
                o.x = acc[mi][ni][half * 2 + 0] + b0v;
                o.y = acc[mi][ni][half * 2 + 1] + b1v;
                *(float2*)(out + (size_t)mrow * DD + ncol) = o;
            }
        }
    }
}

// ===========================================================================
// Flash attention, tf32 mma.sync — 128 q-rows, 4 warps (32 q-rows each),
// 2-stage cp.async KV ring, 1 sync/tile, 2 CTAs/SM, mask reg-cache,
// warp-uniform causal branch.
// ===========================================================================
#define SA 68
#define QR 128
#define KVSTG (2 * 64 * SA)

__global__ __launch_bounds__(128, 2) void attn_mma(const float* __restrict__ mask)
{
    extern __shared__ float smf[];
    float* Qs = smf;                      // [128][SA]
    float* KV = Qs + QR * SA;             // 2 stages x (K[64*SA] + V[64*SA])
    float* Ms = KV + 2 * KVSTG;           // [2048] additive mask row

    const uint32_t* Qu = (const uint32_t*)Qs;
    const uint32_t qs_u = smem_u32(Qs);
    const uint32_t kv_u = smem_u32(KV);

    const int qt = gridDim.x - 1 - blockIdx.x;   // big tiles first
    const int h = blockIdx.y, b = blockIdx.z;
    const int tid = threadIdx.x, warp = tid >> 5, lane = tid & 31;
    const int r = lane >> 2, cq = lane & 3;
    const int wm = warp * 32;                    // 32 rows per warp
    const int q0 = qt * QR;

    const float* kroot = g_k + (size_t)((b * HH + h) * SS) * HD;
    const float* vroot = g_v + (size_t)((b * HH + h) * SS) * HD;

    // Q tile (cp.async): 128 rows x 64, 16 cp16/thread
    const float* qbase = g_q + (size_t)((b * HH + h) * SS + q0) * HD;
#pragma unroll
    for (int p = 0; p < 16; p++) {
        int lin = p * 512 + tid * 4;
        int rr = lin >> 6, dd = lin & 63;
        cp16(qs_u + (uint32_t)(rr * SA + dd) * 4, qbase + rr * 64 + dd);
    }

    auto issue_kv = [&](int jt) {
        int st = jt & 1;
        uint32_t ku = kv_u + (uint32_t)(st * KVSTG) * 4;
        uint32_t vu = ku + (uint32_t)(64 * SA) * 4;
        const float* kb = kroot + (size_t)(jt * 64) * HD;
        const float* vb = vroot + (size_t)(jt * 64) * HD;
#pragma unroll
        for (int p = 0; p < 8; p++) {
            int lin = p * 512 + tid * 4;
            int rr = lin >> 6, dd = lin & 63;
            uint32_t off = (uint32_t)(rr * SA + dd) * 4;
            cp16(ku + off, kb + rr * 64 + dd);
            cp16(vu + off, vb + rr * 64 + dd);
        }
    };

    issue_kv(0);
    CP_COMMIT();     // group: Q + KV0

    // Preload additive mask row (plain stores; visible after first sync)
#pragma unroll
    for (int p = 0; p < 16; p++) {
        int idx = p * 128 + tid;
        Ms[idx] = (1.f - mask[b * SS + idx]) * NEG;
    }

    float o[2][8][4];
#pragma unroll
    for (int mi = 0; mi < 2; mi++)
#pragma unroll
        for (int ni = 0; ni < 8; ni++)
#pragma unroll
            for (int t = 0; t < 4; t++) o[mi][ni][t] = 0.f;
    float mst[2][2] = {{-1e30f, -1e30f}, {-1e30f, -1e30f}};
    float lst[2][2] = {{0.f, 0.f}, {0.f, 0.f}};

    const int jt_max = 2 * qt + 1;
    const int rowbase = q0 + wm;
    const int src0 = (lane & ~3) | (cq >> 1);
    const int src1 = src0 + 2;
    const bool oddl = cq & 1;

    for (int jt = 0; jt <= jt_max; jt++) {
        CP_WAIT(0);          // stage jt resident (prefetched a full tile ago)
        __syncthreads();     // + readers of the other stage (tile jt-1) done

        if (jt < jt_max) { issue_kv(jt + 1); CP_COMMIT(); }

        const uint32_t* Ku = (const uint32_t*)(KV + (jt & 1) * KVSTG);
        const uint32_t* Vu = Ku + 64 * SA;
        const float* madd = Ms + jt * 64;

        // register-cache the 16 mask values this thread needs
        float2 m2[8];
#pragma unroll
        for (int ni = 0; ni < 8; ni++)
            m2[ni] = *(const float2*)&madd[8 * ni + 2 * cq];

        // ---- S = Q @ K^T  (both m-tiles share each K B-fragment)
        float s[2][8][4];
#pragma unroll
        for (int mi = 0; mi < 2; mi++)
#pragma unroll
            for (int ni = 0; ni < 8; ni++)
#pragma unroll
                for (int t = 0; t < 4; t++) s[mi][ni][t] = 0.f;
#pragma unroll
        for (int ks = 0; ks < 8; ks++) {
            const int k = ks * 8;
            uint32_t a0[2], a1[2], a2[2], a3[2];
#pragma unroll
            for (int mi = 0; mi < 2; mi++) {
                int mb = wm + mi * 16;
                a0[mi] = Qu[(mb + r) * SA + k + cq];
                a1[mi] = Qu[(mb + r + 8) * SA + k + cq];
                a2[mi] = Qu[(mb + r) * SA + k + cq + 4];
                a3[mi] = Qu[(mb + r + 8) * SA + k + cq + 4];
            }
#pragma unroll
            for (int ni = 0; ni < 8; ni++) {
                uint32_t b0 = Ku[(8 * ni + r) * SA + k + cq];
                uint32_t b1 = Ku[(8 * ni + r) * SA + k + cq + 4];
                mma_tf32(s[0][ni], a0[0], a1[0], a2[0], a3[0], b0, b1);
                mma_tf32(s[1][ni], a0[1], a1[1], a2[1], a3[1], b0, b1);
            }
        }

        // ---- scale + causal + padding mask (warp-uniform fast path)
        const bool part = (jt * 64 + 63 > rowbase);
        if (!part) {
#pragma unroll
            for (int mi = 0; mi < 2; mi++)
#pragma unroll
                for (int ni = 0; ni < 8; ni++) {
                    s[mi][ni][0] = s[mi][ni][0] * 0.125f + m2[ni].x;
                    s[mi][ni][1] = s[mi][ni][1] * 0.125f + m2[ni].y;
                    s[mi][ni][2] = s[mi][ni][2] * 0.125f + m2[ni].x;
                    s[mi][ni][3] = s[mi][ni][3] * 0.125f + m2[ni].y;
                }
        } else {
            const int colb = jt * 64;
#pragma unroll
            for (int mi = 0; mi < 2; mi++) {
#pragma unroll
                for (int ni = 0; ni < 8; ni++) {
#pragma unroll
                    for (int t = 0; t < 4; t++) {
                        int col = 8 * ni + 2 * cq + (t & 1);
                        int rowg = rowbase + mi * 16 + r + ((t < 2) ? 0 : 8);
                        float mv = (t & 1) ? m2[ni].y : m2[ni].x;
                        float v;
                        if (colb + col > rowg) v = NEG + mv;
                        else                   v = s[mi][ni][t] * 0.125f + mv;
                        s[mi][ni][t] = v;
                    }
                }
            }
        }

        // ---- online softmax
#pragma unroll
        for (int mi = 0; mi < 2; mi++) {
            float mx0 = -1e30f, mx1 = -1e30f;
#pragma unroll
            for (int ni = 0; ni < 8; ni++) {
                mx0 = fmaxf(mx0, fmaxf(s[mi][ni][0], s[mi][ni][1]));
                mx1 = fmaxf(mx1, fmaxf(s[mi][ni][2], s[mi][ni][3]));
            }
            mx0 = fmaxf(mx0, __shfl_xor_sync(0xffffffff, mx0, 1));
            mx0 = fmaxf(mx0, __shfl_xor_sync(0xffffffff, mx0, 2));
            mx1 = fmaxf(mx1, __shfl_xor_sync(0xffffffff, mx1, 1));
            mx1 = fmaxf(mx1, __shfl_xor_sync(0xffffffff, mx1, 2));

            float nm0 = fmaxf(mst[mi][0], mx0), nm1 = fmaxf(mst[mi][1], mx1);
            float sc0 = __expf(mst[mi][0] - nm0), sc1 = __expf(mst[mi][1] - nm1);
            float sum0 = 0.f, sum1 = 0.f;
#pragma unroll
            for (int ni = 0; ni < 8; ni++) {
                s[mi][ni][0] = __expf(s[mi][ni][0] - nm0);
                s[mi][ni][1] = __expf(s[mi][ni][1] - nm0);
                s[mi][ni][2] = __expf(s[mi][ni][2] - nm1);
                s[mi][ni][3] = __expf(s[mi][ni][3] - nm1);
                sum0 += s[mi][ni][0] + s[mi][ni][1];
                sum1 += s[mi][ni][2] + s[mi][ni][3];
            }
            sum0 += __shfl_xor_sync(0xffffffff, sum0, 1);
            sum0 += __shfl_xor_sync(0xffffffff, sum0, 2);
            sum1 += __shfl_xor_sync(0xffffffff, sum1, 1);
            sum1 += __shfl_xor_sync(0xffffffff, sum1, 2);

            lst[mi][0] = lst[mi][0] * sc0 + sum0;  mst[mi][0] = nm0;
            lst[mi][1] = lst[mi][1] * sc1 + sum1;  mst[mi][1] = nm1;

#pragma unroll
            for (int ni = 0; ni < 8; ni++) {
                o[mi][ni][0] *= sc0; o[mi][ni][1] *= sc0;
                o[mi][ni][2] *= sc1; o[mi][ni][3] *= sc1;
            }
        }

        // ---- O += P @ V : shuffle C->A fragment conversion; V shared by mi
#pragma unroll
        for (int ks = 0; ks < 8; ks++) {
            uint32_t pa0[2], pa1[2], pa2[2], pa3[2];
#pragma unroll
            for (int mi = 0; mi < 2; mi++) {
                uint32_t q0r = f2tf32(s[mi][ks][0]), q1r = f2tf32(s[mi][ks][1]);
                uint32_t q2r = f2tf32(s[mi][ks][2]), q3r = f2tf32(s[mi][ks][3]);
                uint32_t x00 = __shfl_sync(0xffffffff, q0r, src0);
                uint32_t x01 = __shfl_sync(0xffffffff, q1r, src0);
                uint32_t x10 = __shfl_sync(0xffffffff, q2r, src0);
                uint32_t x11 = __shfl_sync(0xffffffff, q3r, src0);
                uint32_t x20 = __shfl_sync(0xffffffff, q0r, src1);
                uint32_t x21 = __shfl_sync(0xffffffff, q1r, src1);
                uint32_t x30 = __shfl_sync(0xffffffff, q2r, src1);
                uint32_t x31 = __shfl_sync(0xffffffff, q3r, src1);
                pa0[mi] = oddl ? x01 : x00;
                pa1[mi] = oddl ? x11 : x10;
                pa2[mi] = oddl ? x21 : x20;
                pa3[mi] = oddl ? x31 : x30;
            }
            const int k = ks * 8;
#pragma unroll
            for (int ni = 0; ni < 8; ni++) {
                uint32_t b0 = Vu[(k + cq) * SA + 8 * ni + r];
                uint32_t b1 = Vu[(k + cq + 4) * SA + 8 * ni + r];
                mma_tf32(o[0][ni], pa0[0], pa1[0], pa2[0], pa3[0], b0, b1);
                mma_tf32(o[1][ni], pa0[1], pa1[1], pa2[1], pa3[1], b0, b1);
            }
        }
    }

    // ---- epilogue
#pragma unroll
    for (int mi = 0; mi < 2; mi++) {
        float inv0 = 1.f / lst[mi][0], inv1 = 1.f / lst[mi][1];
        int rw0 = rowbase + mi * 16 + r;
        float* ob0 = g_att + (size_t)(b * SS + rw0) * DD + h * HD;
        float* ob1 = g_att + (size_t)(b * SS + rw0 + 8) * DD + h * HD;
#pragma unroll
        for (int ni = 0; ni < 8; ni++) {
            int col = 8 * ni + 2 * cq;
            float2 w0, w1;
            w0.x = f2tf32f(o[mi][ni][0] * inv0); w0.y = f2tf32f(o[mi][ni][1] * inv0);
            w1.x = f2tf32f(o[mi][ni][2] * inv1); w1.y = f2tf32f(o[mi][ni][3] * inv1);
            *(float2*)(ob0 + col) = w0;
            *(float2*)(ob1 + col) = w1;
        }
    }
}

// ---------------------------------------------------------------------------
extern "C" void kernel_launch(void* const* d_in, const int* in_sizes, int n_in,
                              void* d_out, int out_size)
{
    const float* x    = (const float*)d_in[0];
    const float* mask = (const float*)d_in[1];
    const float* Wq   = (const float*)d_in[2];
    const float* bq   = (const float*)d_in[3];
    const float* Wk   = (const float*)d_in[4];
    const float* bk   = (const float*)d_in[5];
    const float* Wv   = (const float*)d_in[6];
    const float* bv   = (const float*)d_in[7];
    const float* Wo   = (const float*)d_in[8];
    const float* bo   = (const float*)d_in[9];
    float* out = (float*)d_out;

    const int cvt_total = X4 + 4 * W4;
    cvt_all<<<(cvt_total + 255) / 256, 256>>>(x, Wq, Wk, Wv, Wo);

    const int gemm_smem = 3 * (ASZ + BSZ) * sizeof(float);                 // ~107.5 KB
    const int attn_smem = (QR * SA + 2 * KVSTG + SS) * sizeof(float);      // ~110 KB
    cudaFuncSetAttribute(qkv_mma,   cudaFuncAttributeMaxDynamicSharedMemorySize, gemm_smem);
    cudaFuncSetAttribute(oproj_mma, cudaFuncAttributeMaxDynamicSharedMemorySize, gemm_smem);
    cudaFuncSetAttribute(attn_mma,  cudaFuncAttributeMaxDynamicSharedMemorySize, attn_smem);

    dim3 gq(DD / 128, (BB * SS) / 128, 3);
    qkv_mma<<<gq, 128, gemm_smem>>>(bq, bk, bv);

    dim3 ga(SS / QR, HH, BB);
    attn_mma<<<ga, 128, attn_smem>>>(mask);

    dim3 go(DD / 128, (BB * SS) / 128);
    oproj_mma<<<go, 128, gemm_smem>>>(bo, out);
}